// round 11
// baseline (speedup 1.0000x reference)
#include <cuda_runtime.h>
#include <math.h>
#include <stdint.h>

// MoE FFN: T=8192 tokens, D=1024, F=4096, E=8, top-2.
// Inputs: x[T,D] f32, W_gate[E,D] f32, Wg[E,F,D] f32, Wu[E,F,D] f32, Wd[E,D,F] f32.
// Output: [T,D] f32.
// mma.sync m16n8k8 tf32 + ldmatrix + tf32 prepass.
// R11 = R8 (best) with ffn2 re-tiled 256x128 @512 threads to cut L2 traffic 25%.

#define NT 8192
#define DD 1024
#define FF 4096
#define NE 8

#define BM 128
#define BN 128
#define BK 32
#define KSTRIDE 36          // smem row stride in floats (pad 32 -> 36)

// ---------------- scratch ----------------
__device__ int   g_count[NE];
__device__ int   g_pairs[NE][NT];   // pair = token*2 + k
__device__ float g_wts[NE][NT];
__device__ float g_h[(size_t)NT * 2 * FF];     // 256 MiB (tf32-rounded)
__device__ float g_o[(size_t)NT * 2 * DD];     // 64 MiB per-pair outputs
__device__ float g_xc[(size_t)NT * DD];        // tf32-rounded x
__device__ float g_wgc[(size_t)NE * FF * DD];  // tf32-rounded Wg
__device__ float g_wuc[(size_t)NE * FF * DD];
__device__ float g_wdc[(size_t)NE * DD * FF];

// ---------------- helpers ----------------
__device__ __forceinline__ uint32_t smem_u32(const void* p) {
    uint32_t a;
    asm("{ .reg .u64 t; cvta.to.shared.u64 t, %1; cvt.u32.u64 %0, t; }" : "=r"(a) : "l"(p));
    return a;
}
__device__ __forceinline__ float tf32r(float x) {
    uint32_t r; asm("cvt.rna.tf32.f32 %0, %1;" : "=r"(r) : "f"(x));
    return __uint_as_float(r);
}
#define CPA16(dst, src, sz) \
    asm volatile("cp.async.cg.shared.global [%0], [%1], 16, %2;" \
                 :: "r"(dst), "l"(src), "r"(sz) : "memory")
#define CP_COMMIT() asm volatile("cp.async.commit_group;" ::: "memory")
#define CP_WAIT2()  asm volatile("cp.async.wait_group 2;" ::: "memory")

#define MMA_TF32(d, a0, a1, a2, a3, b0, b1) \
    asm volatile("mma.sync.aligned.m16n8k8.row.col.f32.tf32.tf32.f32 " \
        "{%0,%1,%2,%3}, {%4,%5,%6,%7}, {%8,%9}, {%0,%1,%2,%3};" \
        : "+f"((d)[0]), "+f"((d)[1]), "+f"((d)[2]), "+f"((d)[3]) \
        : "r"(a0), "r"(a1), "r"(a2), "r"(a3), "r"(b0), "r"(b1))

#define LDSM4(r0, r1, r2, r3, addr) \
    asm volatile("ldmatrix.sync.aligned.m8n8.x4.shared.b16 {%0,%1,%2,%3}, [%4];" \
        : "=r"(r0), "=r"(r1), "=r"(r2), "=r"(r3) : "r"(addr))

// ---------------- tf32 pre-round pass ----------------
__global__ void cvt_kernel(const float4* __restrict__ src, float4* __restrict__ dst,
                           int n4) {
    int i = blockIdx.x * blockDim.x + threadIdx.x;
    if (i >= n4) return;
    float4 v = src[i];
    v.x = tf32r(v.x); v.y = tf32r(v.y); v.z = tf32r(v.z); v.w = tf32r(v.w);
    dst[i] = v;
}

// ---------------- router ----------------
__global__ void zero_counts_kernel() {
    if (threadIdx.x < NE) g_count[threadIdx.x] = 0;
}

__global__ void router_kernel(const float* __restrict__ x,
                              const float* __restrict__ Wgate) {
    int warp = (blockIdx.x * blockDim.x + threadIdx.x) >> 5;
    int lane = threadIdx.x & 31;
    if (warp >= NT) return;
    const float* xr = x + (size_t)warp * DD;

    float lg[NE];
#pragma unroll
    for (int e = 0; e < NE; e++) {
        const float* w = Wgate + e * DD;
        float acc = 0.f;
#pragma unroll 8
        for (int i = lane; i < DD; i += 32) acc = fmaf(xr[i], w[i], acc);
#pragma unroll
        for (int o = 16; o; o >>= 1) acc += __shfl_xor_sync(0xffffffffu, acc, o);
        lg[e] = acc;
    }
    if (lane == 0) {
        int e0 = 0;
#pragma unroll
        for (int e = 1; e < NE; e++) if (lg[e] > lg[e0]) e0 = e;
        int e1 = (e0 == 0) ? 1 : 0;
#pragma unroll
        for (int e = 0; e < NE; e++) {
            if (e == e0 || e == e1) continue;
            if (lg[e] > lg[e1]) e1 = e;
        }
        float w0 = 1.f / (1.f + expf(lg[e1] - lg[e0]));
        float w1 = 1.f - w0;
        int p0 = atomicAdd(&g_count[e0], 1);
        g_pairs[e0][p0] = warp * 2;     g_wts[e0][p0] = w0;
        int p1 = atomicAdd(&g_count[e1], 1);
        g_pairs[e1][p1] = warp * 2 + 1; g_wts[e1][p1] = w1;
    }
}

// ---------------- GEMM1: gate+up fused (R8 config, unchanged) ----------------
// dyn smem floats: stage s (0..2) at s*13824: A[128][36] @0, Bg @4608, Bu @9216
// sp[] at float offset 41472.  Bytes = 165888 + 512.
#define ST1 13824
#define SMEM1_BYTES (165888 + 512)

__global__ void __launch_bounds__(256, 1) ffn1_mma() {
    const int e   = blockIdx.z;
    const int cnt = g_count[e];
    const int m0  = blockIdx.x * BM;
    if (m0 >= cnt) return;
    const int n0  = blockIdx.y * BN;

    extern __shared__ float S[];
    int* sp = (int*)(S + 41472);
    const uint32_t sb = smem_u32(S);
    const int tid = threadIdx.x;

    if (tid < BM) {
        int s = m0 + tid;
        sp[tid] = (s < cnt) ? g_pairs[e][s] : -1;
    }
    __syncthreads();

    const int r0 = tid >> 3;
    const int c4 = (tid & 7) * 4;
    const float* ap[4];
    uint32_t asz[4];
#pragma unroll
    for (int i = 0; i < 4; i++) {
        int p = sp[r0 + 32 * i];
        asz[i] = (p >= 0) ? 16u : 0u;
        ap[i] = g_xc + (size_t)((p >= 0) ? (p >> 1) : 0) * DD + c4;
    }
    const float* wgb = g_wgc + (size_t)e * FF * DD + (size_t)(n0 + r0) * DD + c4;
    const float* wub = g_wuc + (size_t)e * FF * DD + (size_t)(n0 + r0) * DD + c4;
    const uint32_t rowb = (uint32_t)(r0 * KSTRIDE + c4) * 4u;

    const int lane = tid & 31;
    const int g  = lane >> 2;
    const int tg = lane & 3;
    const int wm = (tid >> 5) & 3;
    const int wn = tid >> 7;

    const int lt = lane >> 3;
    const int tr = lane & 7;
    uint32_t aoff[2];
#pragma unroll
    for (int i = 0; i < 2; i++) {
        int row = wm * 32 + i * 16 + (lt & 1) * 8 + tr;
        aoff[i] = (uint32_t)(row * KSTRIDE + (lt >> 1) * 4) * 4u;
    }
    uint32_t boff[4];
#pragma unroll
    for (int p = 0; p < 4; p++) {
        int row = wn * 64 + p * 16 + (lt >> 1) * 8 + tr;
        boff[p] = (uint32_t)(row * KSTRIDE + (lt & 1) * 4) * 4u;
    }

    float accg[2][8][4], accu[2][8][4];
#pragma unroll
    for (int i = 0; i < 2; i++)
#pragma unroll
        for (int j = 0; j < 8; j++)
#pragma unroll
            for (int q = 0; q < 4; q++) { accg[i][j][q] = 0.f; accu[i][j][q] = 0.f; }

    const int NC = DD / BK;   // 32

    auto fill = [&](int ch) {
        const uint32_t so = (uint32_t)(ch % 3) * ((uint32_t)ST1 * 4u);
        const int k0 = ch * BK;
        uint32_t sA = sb + so + rowb;
        uint32_t sG = sA + 4608u * 4u;
        uint32_t sU = sA + 9216u * 4u;
#pragma unroll
        for (int i = 0; i < 4; i++) {
            CPA16(sA + i * (32u * KSTRIDE * 4u), ap[i] + k0, asz[i]);
            CPA16(sG + i * (32u * KSTRIDE * 4u), wgb + (size_t)i * 32 * DD + k0, 16u);
            CPA16(sU + i * (32u * KSTRIDE * 4u), wub + (size_t)i * 32 * DD + k0, 16u);
        }
    };

    fill(0); CP_COMMIT();
    fill(1); CP_COMMIT();

    for (int c = 0; c < NC; c++) {
        if (c + 2 < NC) fill(c + 2);
        CP_COMMIT();
        CP_WAIT2();
        __syncthreads();

        const uint32_t stg = sb + (uint32_t)(c % 3) * ((uint32_t)ST1 * 4u);
        const uint32_t sG  = stg + 4608u * 4u;
        const uint32_t sU  = stg + 9216u * 4u;

#pragma unroll
        for (int s = 0; s < 4; s++) {
            const uint32_t kb = (uint32_t)s * 32u;
            uint32_t af[2][4];
            LDSM4(af[0][0], af[0][1], af[0][2], af[0][3], stg + aoff[0] + kb);
            LDSM4(af[1][0], af[1][1], af[1][2], af[1][3], stg + aoff[1] + kb);
#pragma unroll
            for (int p = 0; p < 4; p++) {
                uint32_t bg0, bg1, bg2, bg3, bu0, bu1, bu2, bu3;
                LDSM4(bg0, bg1, bg2, bg3, sG + boff[p] + kb);
                LDSM4(bu0, bu1, bu2, bu3, sU + boff[p] + kb);
                const int j0 = p * 2, j1 = p * 2 + 1;
                MMA_TF32(accg[0][j0], af[0][0], af[0][1], af[0][2], af[0][3], bg0, bg1);
                MMA_TF32(accg[1][j0], af[1][0], af[1][1], af[1][2], af[1][3], bg0, bg1);
                MMA_TF32(accg[0][j1], af[0][0], af[0][1], af[0][2], af[0][3], bg2, bg3);
                MMA_TF32(accg[1][j1], af[1][0], af[1][1], af[1][2], af[1][3], bg2, bg3);
                MMA_TF32(accu[0][j0], af[0][0], af[0][1], af[0][2], af[0][3], bu0, bu1);
                MMA_TF32(accu[1][j0], af[1][0], af[1][1], af[1][2], af[1][3], bu0, bu1);
                MMA_TF32(accu[0][j1], af[0][0], af[0][1], af[0][2], af[0][3], bu2, bu3);
                MMA_TF32(accu[1][j1], af[1][0], af[1][1], af[1][2], af[1][3], bu2, bu3);
            }
        }
        __syncthreads();
    }

#pragma unroll
    for (int i = 0; i < 2; i++) {
#pragma unroll
        for (int half = 0; half < 2; half++) {
            const int rl = wm * 32 + i * 16 + g + half * 8;
            const int pr = sp[rl];
            if (pr < 0) continue;
            float* hrow = g_h + (size_t)pr * FF + n0 + wn * 64 + 2 * tg;
#pragma unroll
            for (int j = 0; j < 8; j++) {
                float gv0 = accg[i][j][half * 2 + 0];
                float gv1 = accg[i][j][half * 2 + 1];
                float2 hv;
                hv.x = tf32r(gv0 / (1.f + expf(-gv0)) * accu[i][j][half * 2 + 0]);
                hv.y = tf32r(gv1 / (1.f + expf(-gv1)) * accu[i][j][half * 2 + 1]);
                *(float2*)(hrow + j * 8) = hv;
            }
        }
    }
}

// ---------------- GEMM2: down proj, 256x128 tile, 512 threads ----------------
// dyn smem floats: stage s (0..2) at s*13824: A[256][36] @0, B[128][36] @9216
// sp at float 41472 (256 ints), sw at 41728 (256 floats).
// Bytes = 165888 + 2048 = 167936.
#define BM2 256
#define ST2 13824
#define SMEM2_BYTES (165888 + 2048)

__global__ void __launch_bounds__(512, 1) ffn2_mma() {
    const int e   = blockIdx.z;
    const int cnt = g_count[e];
    const int m0  = blockIdx.x * BM2;
    if (m0 >= cnt) return;
    const int n0  = blockIdx.y * BN;   // over D

    extern __shared__ float S[];
    int*   sp = (int*)(S + 41472);
    float* sw = S + 41728;
    const uint32_t sb = smem_u32(S);
    const int tid = threadIdx.x;

    if (tid < BM2) {
        int s = m0 + tid;
        sp[tid] = (s < cnt) ? g_pairs[e][s] : -1;
        sw[tid] = (s < cnt) ? g_wts[e][s] : 0.f;
    }
    __syncthreads();

    // A fill: rows r0a+64i (i=0..3), cols [c4, c4+4)
    const int r0a = tid >> 3;          // 0..63
    const int c4  = (tid & 7) * 4;
    const float* ap[4];
    uint32_t asz[4];
#pragma unroll
    for (int i = 0; i < 4; i++) {
        int p = sp[r0a + 64 * i];
        asz[i] = (p >= 0) ? 16u : 0u;
        ap[i] = g_h + (size_t)((p >= 0) ? p : 0) * FF + c4;
    }
    const uint32_t rowbA = (uint32_t)(r0a * KSTRIDE + c4) * 4u;

    // B fill: row r0b (0..127), cols [cb8, cb8+8): two float4s
    const int r0b = tid >> 2;          // 0..127
    const int cb8 = (tid & 3) * 8;
    const float* wb = g_wdc + (size_t)e * DD * FF + (size_t)(n0 + r0b) * FF + cb8;
    const uint32_t rowbB = (uint32_t)(r0b * KSTRIDE + cb8) * 4u;

    const int lane = tid & 31;
    const int g  = lane >> 2;
    const int tg = lane & 3;
    const int wid = tid >> 5;
    const int wm = wid & 7;            // 8 m-warps (32 rows each)
    const int wn = wid >> 3;           // 2 n-warps (64 cols each)

    const int lt = lane >> 3;
    const int tr = lane & 7;
    uint32_t aoff[2];
#pragma unroll
    for (int i = 0; i < 2; i++) {
        int row = wm * 32 + i * 16 + (lt & 1) * 8 + tr;
        aoff[i] = (uint32_t)(row * KSTRIDE + (lt >> 1) * 4) * 4u;
    }
    uint32_t boff[4];
#pragma unroll
    for (int p = 0; p < 4; p++) {
        int row = wn * 64 + p * 16 + (lt >> 1) * 8 + tr;
        boff[p] = (uint32_t)(row * KSTRIDE + (lt & 1) * 4) * 4u + 9216u * 4u;
    }

    float acc[2][8][4];
#pragma unroll
    for (int i = 0; i < 2; i++)
#pragma unroll
        for (int j = 0; j < 8; j++)
#pragma unroll
            for (int q = 0; q < 4; q++) acc[i][j][q] = 0.f;

    const int NC = FF / BK;   // 128

    auto fill = [&](int ch) {
        const uint32_t so = (uint32_t)(ch % 3) * ((uint32_t)ST2 * 4u);
        const int k0 = ch * BK;
        uint32_t sA = sb + so + rowbA;
#pragma unroll
        for (int i = 0; i < 4; i++)
            CPA16(sA + i * (64u * KSTRIDE * 4u), ap[i] + k0, asz[i]);
        uint32_t sB = sb + so + 9216u * 4u + rowbB;
        CPA16(sB,       wb + k0,     16u);
        CPA16(sB + 16u, wb + k0 + 4, 16u);
    };

    fill(0); CP_COMMIT();
    fill(1); CP_COMMIT();

    for (int c = 0; c < NC; c++) {
        if (c + 2 < NC) fill(c + 2);
        CP_COMMIT();
        CP_WAIT2();
        __syncthreads();

        const uint32_t stg = sb + (uint32_t)(c % 3) * ((uint32_t)ST2 * 4u);

#pragma unroll
        for (int s = 0; s < 4; s++) {
            const uint32_t kb = (uint32_t)s * 32u;
            uint32_t af[2][4];
            LDSM4(af[0][0], af[0][1], af[0][2], af[0][3], stg + aoff[0] + kb);
            LDSM4(af[1][0], af[1][1], af[1][2], af[1][3], stg + aoff[1] + kb);
#pragma unroll
            for (int p = 0; p < 4; p++) {
                uint32_t b0, b1, b2, b3;
                LDSM4(b0, b1, b2, b3, stg + boff[p] + kb);
                const int j0 = p * 2, j1 = p * 2 + 1;
                MMA_TF32(acc[0][j0], af[0][0], af[0][1], af[0][2], af[0][3], b0, b1);
                MMA_TF32(acc[1][j0], af[1][0], af[1][1], af[1][2], af[1][3], b0, b1);
                MMA_TF32(acc[0][j1], af[0][0], af[0][1], af[0][2], af[0][3], b2, b3);
                MMA_TF32(acc[1][j1], af[1][0], af[1][1], af[1][2], af[1][3], b2, b3);
            }
        }
        __syncthreads();
    }

    // epilogue: g_o[pair] = acc * w
#pragma unroll
    for (int i = 0; i < 2; i++) {
#pragma unroll
        for (int half = 0; half < 2; half++) {
            const int rl = wm * 32 + i * 16 + g + half * 8;
            const int pr = sp[rl];
            if (pr < 0) continue;
            const float w = sw[rl];
            float* orow = g_o + (size_t)pr * DD + n0 + wn * 64 + 2 * tg;
#pragma unroll
            for (int j = 0; j < 8; j++) {
                float2 ov;
                ov.x = acc[i][j][half * 2 + 0] * w;
                ov.y = acc[i][j][half * 2 + 1] * w;
                *(float2*)(orow + j * 8) = ov;
            }
        }
    }
}

// ---------------- combine: out[t] = g_o[2t] + g_o[2t+1] ----------------
__global__ void combine_kernel(float4* __restrict__ out) {
    int i = blockIdx.x * blockDim.x + threadIdx.x;
    if (i >= NT * DD / 4) return;
    const int t  = i / (DD / 4);
    const int d4 = i % (DD / 4);
    const float4* a = (const float4*)(g_o + (size_t)(2 * t) * DD) + d4;
    const float4* b = (const float4*)(g_o + (size_t)(2 * t + 1) * DD) + d4;
    float4 va = *a, vb = *b;
    va.x += vb.x; va.y += vb.y; va.z += vb.z; va.w += vb.w;
    out[i] = va;
}

// ---------------------------------------------------------------------------
extern "C" void kernel_launch(void* const* d_in, const int* in_sizes, int n_in,
                              void* d_out, int out_size) {
    const float* x     = (const float*)d_in[0];
    const float* Wgate = (const float*)d_in[1];
    const float* Wg    = (const float*)d_in[2];
    const float* Wu    = (const float*)d_in[3];
    const float* Wd    = (const float*)d_in[4];
    float* out = (float*)d_out;

    cudaFuncSetAttribute(ffn1_mma, cudaFuncAttributeMaxDynamicSharedMemorySize, SMEM1_BYTES);
    cudaFuncSetAttribute(ffn2_mma, cudaFuncAttributeMaxDynamicSharedMemorySize, SMEM2_BYTES);

    // tf32 pre-round copies
    float *g_xc_p, *g_wgc_p, *g_wuc_p, *g_wdc_p;
    cudaGetSymbolAddress((void**)&g_xc_p,  g_xc);
    cudaGetSymbolAddress((void**)&g_wgc_p, g_wgc);
    cudaGetSymbolAddress((void**)&g_wuc_p, g_wuc);
    cudaGetSymbolAddress((void**)&g_wdc_p, g_wdc);

    const int n4x = NT * DD / 4;
    const int n4w = NE * FF * DD / 4;
    cvt_kernel<<<(n4x + 255) / 256, 256>>>((const float4*)x,  (float4*)g_xc_p,  n4x);
    cvt_kernel<<<(n4w + 255) / 256, 256>>>((const float4*)Wg, (float4*)g_wgc_p, n4w);
    cvt_kernel<<<(n4w + 255) / 256, 256>>>((const float4*)Wu, (float4*)g_wuc_p, n4w);
    cvt_kernel<<<(n4w + 255) / 256, 256>>>((const float4*)Wd, (float4*)g_wdc_p, n4w);

    zero_counts_kernel<<<1, 32>>>();
    router_kernel<<<NT / 8, 256>>>(x, Wgate);

    dim3 g1(NT / BM, FF / BN, NE);           // 64 x 32 x 8
    ffn1_mma<<<g1, 256, SMEM1_BYTES>>>();

    dim3 g2(NT / BM2, DD / BN, NE);          // 32 x 8 x 8
    ffn2_mma<<<g2, 512, SMEM2_BYTES>>>();

    combine_kernel<<<(NT * DD / 4 + 255) / 256, 256>>>((float4*)out);
}

// round 14
// speedup vs baseline: 1.2073x; 1.2073x over previous
#include <cuda_runtime.h>
#include <math.h>
#include <stdint.h>

// MoE FFN: T=8192 tokens, D=1024, F=4096, E=8, top-2.
// Inputs: x[T,D] f32, W_gate[E,D] f32, Wg[E,F,D] f32, Wu[E,F,D] f32, Wd[E,D,F] f32.
// Output: [T,D] f32.
// mma.sync m16n8k8 tf32 + ldmatrix + tf32 prepass (R8 tiles).
// R12: single-barrier pipeline (fill after compute, 3 stages, one __syncthreads
//      per chunk); launch order puts ffn1 at ncu's profiled slot.

#define NT 8192
#define DD 1024
#define FF 4096
#define NE 8

#define BM 128
#define BN 128
#define BK 32
#define KSTRIDE 36          // smem row stride in floats (pad 32 -> 36)

// ---------------- scratch ----------------
__device__ int   g_count[NE];
__device__ int   g_pairs[NE][NT];   // pair = token*2 + k
__device__ float g_wts[NE][NT];
__device__ float g_h[(size_t)NT * 2 * FF];     // 256 MiB (tf32-rounded)
__device__ float g_o[(size_t)NT * 2 * DD];     // 64 MiB per-pair outputs
__device__ float g_xc[(size_t)NT * DD];        // tf32-rounded x
__device__ float g_wgc[(size_t)NE * FF * DD];  // tf32-rounded Wg
__device__ float g_wuc[(size_t)NE * FF * DD];
__device__ float g_wdc[(size_t)NE * DD * FF];

// ---------------- helpers ----------------
__device__ __forceinline__ uint32_t smem_u32(const void* p) {
    uint32_t a;
    asm("{ .reg .u64 t; cvta.to.shared.u64 t, %1; cvt.u32.u64 %0, t; }" : "=r"(a) : "l"(p));
    return a;
}
__device__ __forceinline__ float tf32r(float x) {
    uint32_t r; asm("cvt.rna.tf32.f32 %0, %1;" : "=r"(r) : "f"(x));
    return __uint_as_float(r);
}
#define CPA16(dst, src, sz) \
    asm volatile("cp.async.cg.shared.global [%0], [%1], 16, %2;" \
                 :: "r"(dst), "l"(src), "r"(sz) : "memory")
#define CP_COMMIT() asm volatile("cp.async.commit_group;" ::: "memory")
#define CP_WAIT1()  asm volatile("cp.async.wait_group 1;" ::: "memory")

#define MMA_TF32(d, a0, a1, a2, a3, b0, b1) \
    asm volatile("mma.sync.aligned.m16n8k8.row.col.f32.tf32.tf32.f32 " \
        "{%0,%1,%2,%3}, {%4,%5,%6,%7}, {%8,%9}, {%0,%1,%2,%3};" \
        : "+f"((d)[0]), "+f"((d)[1]), "+f"((d)[2]), "+f"((d)[3]) \
        : "r"(a0), "r"(a1), "r"(a2), "r"(a3), "r"(b0), "r"(b1))

#define LDSM4(r0, r1, r2, r3, addr) \
    asm volatile("ldmatrix.sync.aligned.m8n8.x4.shared.b16 {%0,%1,%2,%3}, [%4];" \
        : "=r"(r0), "=r"(r1), "=r"(r2), "=r"(r3) : "r"(addr))

// ---------------- tf32 pre-round pass ----------------
__global__ void cvt_kernel(const float4* __restrict__ src, float4* __restrict__ dst,
                           int n4) {
    int i = blockIdx.x * blockDim.x + threadIdx.x;
    if (i >= n4) return;
    float4 v = src[i];
    v.x = tf32r(v.x); v.y = tf32r(v.y); v.z = tf32r(v.z); v.w = tf32r(v.w);
    dst[i] = v;
}

// ---------------- router ----------------
__global__ void zero_counts_kernel() {
    if (threadIdx.x < NE) g_count[threadIdx.x] = 0;
}

__global__ void router_kernel(const float* __restrict__ x,
                              const float* __restrict__ Wgate) {
    int warp = (blockIdx.x * blockDim.x + threadIdx.x) >> 5;
    int lane = threadIdx.x & 31;
    if (warp >= NT) return;
    const float* xr = x + (size_t)warp * DD;

    float lg[NE];
#pragma unroll
    for (int e = 0; e < NE; e++) {
        const float* w = Wgate + e * DD;
        float acc = 0.f;
#pragma unroll 8
        for (int i = lane; i < DD; i += 32) acc = fmaf(xr[i], w[i], acc);
#pragma unroll
        for (int o = 16; o; o >>= 1) acc += __shfl_xor_sync(0xffffffffu, acc, o);
        lg[e] = acc;
    }
    if (lane == 0) {
        int e0 = 0;
#pragma unroll
        for (int e = 1; e < NE; e++) if (lg[e] > lg[e0]) e0 = e;
        int e1 = (e0 == 0) ? 1 : 0;
#pragma unroll
        for (int e = 0; e < NE; e++) {
            if (e == e0 || e == e1) continue;
            if (lg[e] > lg[e1]) e1 = e;
        }
        float w0 = 1.f / (1.f + expf(lg[e1] - lg[e0]));
        float w1 = 1.f - w0;
        int p0 = atomicAdd(&g_count[e0], 1);
        g_pairs[e0][p0] = warp * 2;     g_wts[e0][p0] = w0;
        int p1 = atomicAdd(&g_count[e1], 1);
        g_pairs[e1][p1] = warp * 2 + 1; g_wts[e1][p1] = w1;
    }
}

// ---------------- GEMM1: gate+up fused (R8 tiles, single-barrier) ----------------
// dyn smem floats: stage s (0..2) at s*13824: A[128][36] @0, Bg @4608, Bu @9216
// sp[] at float offset 41472.  Bytes = 165888 + 512.
#define ST1 13824
#define SMEM1_BYTES (165888 + 512)

__global__ void __launch_bounds__(256, 1) ffn1_mma() {
    const int e   = blockIdx.z;
    const int cnt = g_count[e];
    const int m0  = blockIdx.x * BM;
    if (m0 >= cnt) return;
    const int n0  = blockIdx.y * BN;

    extern __shared__ float S[];
    int* sp = (int*)(S + 41472);
    const uint32_t sb = smem_u32(S);
    const int tid = threadIdx.x;

    if (tid < BM) {
        int s = m0 + tid;
        sp[tid] = (s < cnt) ? g_pairs[e][s] : -1;
    }
    __syncthreads();

    const int r0 = tid >> 3;
    const int c4 = (tid & 7) * 4;
    const float* ap[4];
    uint32_t asz[4];
#pragma unroll
    for (int i = 0; i < 4; i++) {
        int p = sp[r0 + 32 * i];
        asz[i] = (p >= 0) ? 16u : 0u;
        ap[i] = g_xc + (size_t)((p >= 0) ? (p >> 1) : 0) * DD + c4;
    }
    const float* wgb = g_wgc + (size_t)e * FF * DD + (size_t)(n0 + r0) * DD + c4;
    const float* wub = g_wuc + (size_t)e * FF * DD + (size_t)(n0 + r0) * DD + c4;
    const uint32_t rowb = (uint32_t)(r0 * KSTRIDE + c4) * 4u;

    const int lane = tid & 31;
    const int g  = lane >> 2;
    const int tg = lane & 3;
    const int wm = (tid >> 5) & 3;
    const int wn = tid >> 7;

    const int lt = lane >> 3;
    const int tr = lane & 7;
    uint32_t aoff[2];
#pragma unroll
    for (int i = 0; i < 2; i++) {
        int row = wm * 32 + i * 16 + (lt & 1) * 8 + tr;
        aoff[i] = (uint32_t)(row * KSTRIDE + (lt >> 1) * 4) * 4u;
    }
    uint32_t boff[4];
#pragma unroll
    for (int p = 0; p < 4; p++) {
        int row = wn * 64 + p * 16 + (lt >> 1) * 8 + tr;
        boff[p] = (uint32_t)(row * KSTRIDE + (lt & 1) * 4) * 4u;
    }

    float accg[2][8][4], accu[2][8][4];
#pragma unroll
    for (int i = 0; i < 2; i++)
#pragma unroll
        for (int j = 0; j < 8; j++)
#pragma unroll
            for (int q = 0; q < 4; q++) { accg[i][j][q] = 0.f; accu[i][j][q] = 0.f; }

    const int NC = DD / BK;   // 32

    auto fill = [&](int ch) {
        const uint32_t so = (uint32_t)(ch % 3) * ((uint32_t)ST1 * 4u);
        const int k0 = ch * BK;
        uint32_t sA = sb + so + rowb;
        uint32_t sG = sA + 4608u * 4u;
        uint32_t sU = sA + 9216u * 4u;
#pragma unroll
        for (int i = 0; i < 4; i++) {
            CPA16(sA + i * (32u * KSTRIDE * 4u), ap[i] + k0, asz[i]);
            CPA16(sG + i * (32u * KSTRIDE * 4u), wgb + (size_t)i * 32 * DD + k0, 16u);
            CPA16(sU + i * (32u * KSTRIDE * 4u), wub + (size_t)i * 32 * DD + k0, 16u);
        }
    };

    fill(0); CP_COMMIT();
    fill(1); CP_COMMIT();

    for (int c = 0; c < NC; c++) {
        CP_WAIT1();           // stage c resident
        __syncthreads();      // single barrier per chunk

        const uint32_t stg = sb + (uint32_t)(c % 3) * ((uint32_t)ST1 * 4u);
        const uint32_t sG  = stg + 4608u * 4u;
        const uint32_t sU  = stg + 9216u * 4u;

#pragma unroll
        for (int s = 0; s < 4; s++) {
            const uint32_t kb = (uint32_t)s * 32u;
            uint32_t af[2][4];
            LDSM4(af[0][0], af[0][1], af[0][2], af[0][3], stg + aoff[0] + kb);
            LDSM4(af[1][0], af[1][1], af[1][2], af[1][3], stg + aoff[1] + kb);
#pragma unroll
            for (int p = 0; p < 4; p++) {
                uint32_t bg0, bg1, bg2, bg3, bu0, bu1, bu2, bu3;
                LDSM4(bg0, bg1, bg2, bg3, sG + boff[p] + kb);
                LDSM4(bu0, bu1, bu2, bu3, sU + boff[p] + kb);
                const int j0 = p * 2, j1 = p * 2 + 1;
                MMA_TF32(accg[0][j0], af[0][0], af[0][1], af[0][2], af[0][3], bg0, bg1);
                MMA_TF32(accg[1][j0], af[1][0], af[1][1], af[1][2], af[1][3], bg0, bg1);
                MMA_TF32(accg[0][j1], af[0][0], af[0][1], af[0][2], af[0][3], bg2, bg3);
                MMA_TF32(accg[1][j1], af[1][0], af[1][1], af[1][2], af[1][3], bg2, bg3);
                MMA_TF32(accu[0][j0], af[0][0], af[0][1], af[0][2], af[0][3], bu0, bu1);
                MMA_TF32(accu[1][j0], af[1][0], af[1][1], af[1][2], af[1][3], bu0, bu1);
                MMA_TF32(accu[0][j1], af[0][0], af[0][1], af[0][2], af[0][3], bu2, bu3);
                MMA_TF32(accu[1][j1], af[1][0], af[1][1], af[1][2], af[1][3], bu2, bu3);
            }
        }

        // fill next+1 stage AFTER compute: writes (c+2)%3, safe vs laggards
        if (c + 2 < NC) fill(c + 2);
        CP_COMMIT();
    }

#pragma unroll
    for (int i = 0; i < 2; i++) {
#pragma unroll
        for (int half = 0; half < 2; half++) {
            const int rl = wm * 32 + i * 16 + g + half * 8;
            const int pr = sp[rl];
            if (pr < 0) continue;
            float* hrow = g_h + (size_t)pr * FF + n0 + wn * 64 + 2 * tg;
#pragma unroll
            for (int j = 0; j < 8; j++) {
                float gv0 = accg[i][j][half * 2 + 0];
                float gv1 = accg[i][j][half * 2 + 1];
                float2 hv;
                hv.x = tf32r(gv0 / (1.f + expf(-gv0)) * accu[i][j][half * 2 + 0]);
                hv.y = tf32r(gv1 / (1.f + expf(-gv1)) * accu[i][j][half * 2 + 1]);
                *(float2*)(hrow + j * 8) = hv;
            }
        }
    }
}

// ---------------- GEMM2: down proj (R8 tiles, single-barrier) ----------------
// dyn smem floats: stage s (0..2) at s*9216: A[128][36] @0, B @4608
// sp at float 27648, sw at 27776. Bytes = 110592 + 1024.
#define ST2 9216
#define SMEM2_BYTES (110592 + 1024)

__global__ void __launch_bounds__(256, 2) ffn2_mma() {
    const int e   = blockIdx.z;
    const int cnt = g_count[e];
    const int m0  = blockIdx.x * BM;
    if (m0 >= cnt) return;
    const int n0  = blockIdx.y * BN;   // over D

    extern __shared__ float S[];
    int*   sp = (int*)(S + 27648);
    float* sw = S + 27776;
    const uint32_t sb = smem_u32(S);
    const int tid = threadIdx.x;

    if (tid < BM) {
        int s = m0 + tid;
        sp[tid] = (s < cnt) ? g_pairs[e][s] : -1;
        sw[tid] = (s < cnt) ? g_wts[e][s] : 0.f;
    }
    __syncthreads();

    const int r0 = tid >> 3;
    const int c4 = (tid & 7) * 4;
    const float* ap[4];
    uint32_t asz[4];
#pragma unroll
    for (int i = 0; i < 4; i++) {
        int p = sp[r0 + 32 * i];
        asz[i] = (p >= 0) ? 16u : 0u;
        ap[i] = g_h + (size_t)((p >= 0) ? p : 0) * FF + c4;
    }
    const float* wb = g_wdc + (size_t)e * DD * FF + (size_t)(n0 + r0) * FF + c4;
    const uint32_t rowb = (uint32_t)(r0 * KSTRIDE + c4) * 4u;

    const int lane = tid & 31;
    const int g  = lane >> 2;
    const int tg = lane & 3;
    const int wm = (tid >> 5) & 3;
    const int wn = tid >> 7;

    const int lt = lane >> 3;
    const int tr = lane & 7;
    uint32_t aoff[2];
#pragma unroll
    for (int i = 0; i < 2; i++) {
        int row = wm * 32 + i * 16 + (lt & 1) * 8 + tr;
        aoff[i] = (uint32_t)(row * KSTRIDE + (lt >> 1) * 4) * 4u;
    }
    uint32_t boff[4];
#pragma unroll
    for (int p = 0; p < 4; p++) {
        int row = wn * 64 + p * 16 + (lt >> 1) * 8 + tr;
        boff[p] = (uint32_t)(row * KSTRIDE + (lt & 1) * 4) * 4u;
    }

    float acc[2][8][4];
#pragma unroll
    for (int i = 0; i < 2; i++)
#pragma unroll
        for (int j = 0; j < 8; j++)
#pragma unroll
            for (int q = 0; q < 4; q++) acc[i][j][q] = 0.f;

    const int NC = FF / BK;   // 128

    auto fill = [&](int ch) {
        const uint32_t so = (uint32_t)(ch % 3) * ((uint32_t)ST2 * 4u);
        const int k0 = ch * BK;
        uint32_t sA = sb + so + rowb;
        uint32_t sB = sA + 4608u * 4u;
#pragma unroll
        for (int i = 0; i < 4; i++) {
            CPA16(sA + i * (32u * KSTRIDE * 4u), ap[i] + k0, asz[i]);
            CPA16(sB + i * (32u * KSTRIDE * 4u), wb + (size_t)i * 32 * FF + k0, 16u);
        }
    };

    fill(0); CP_COMMIT();
    fill(1); CP_COMMIT();

    for (int c = 0; c < NC; c++) {
        CP_WAIT1();
        __syncthreads();

        const uint32_t stg = sb + (uint32_t)(c % 3) * ((uint32_t)ST2 * 4u);
        const uint32_t sB  = stg + 4608u * 4u;

#pragma unroll
        for (int s = 0; s < 4; s++) {
            const uint32_t kb = (uint32_t)s * 32u;
            uint32_t af[2][4];
            LDSM4(af[0][0], af[0][1], af[0][2], af[0][3], stg + aoff[0] + kb);
            LDSM4(af[1][0], af[1][1], af[1][2], af[1][3], stg + aoff[1] + kb);
#pragma unroll
            for (int p = 0; p < 4; p++) {
                uint32_t b0, b1, b2, b3;
                LDSM4(b0, b1, b2, b3, sB + boff[p] + kb);
                const int j0 = p * 2, j1 = p * 2 + 1;
                MMA_TF32(acc[0][j0], af[0][0], af[0][1], af[0][2], af[0][3], b0, b1);
                MMA_TF32(acc[1][j0], af[1][0], af[1][1], af[1][2], af[1][3], b0, b1);
                MMA_TF32(acc[0][j1], af[0][0], af[0][1], af[0][2], af[0][3], b2, b3);
                MMA_TF32(acc[1][j1], af[1][0], af[1][1], af[1][2], af[1][3], b2, b3);
            }
        }

        if (c + 2 < NC) fill(c + 2);
        CP_COMMIT();
    }

    // epilogue: g_o[pair] = acc * w  (plain stores; combine kernel sums)
#pragma unroll
    for (int i = 0; i < 2; i++) {
#pragma unroll
        for (int half = 0; half < 2; half++) {
            const int rl = wm * 32 + i * 16 + g + half * 8;
            const int pr = sp[rl];
            if (pr < 0) continue;
            const float w = sw[rl];
            float* orow = g_o + (size_t)pr * DD + n0 + wn * 64 + 2 * tg;
#pragma unroll
            for (int j = 0; j < 8; j++) {
                float2 ov;
                ov.x = acc[i][j][half * 2 + 0] * w;
                ov.y = acc[i][j][half * 2 + 1] * w;
                *(float2*)(orow + j * 8) = ov;
            }
        }
    }
}

// ---------------- combine: out[t] = g_o[2t] + g_o[2t+1] ----------------
__global__ void combine_kernel(float4* __restrict__ out) {
    int i = blockIdx.x * blockDim.x + threadIdx.x;
    if (i >= NT * DD / 4) return;
    const int t  = i / (DD / 4);
    const int d4 = i % (DD / 4);
    const float4* a = (const float4*)(g_o + (size_t)(2 * t) * DD) + d4;
    const float4* b = (const float4*)(g_o + (size_t)(2 * t + 1) * DD) + d4;
    float4 va = *a, vb = *b;
    va.x += vb.x; va.y += vb.y; va.z += vb.z; va.w += vb.w;
    out[i] = va;
}

// ---------------------------------------------------------------------------
extern "C" void kernel_launch(void* const* d_in, const int* in_sizes, int n_in,
                              void* d_out, int out_size) {
    const float* x     = (const float*)d_in[0];
    const float* Wgate = (const float*)d_in[1];
    const float* Wg    = (const float*)d_in[2];
    const float* Wu    = (const float*)d_in[3];
    const float* Wd    = (const float*)d_in[4];
    float* out = (float*)d_out;

    cudaFuncSetAttribute(ffn1_mma, cudaFuncAttributeMaxDynamicSharedMemorySize, SMEM1_BYTES);
    cudaFuncSetAttribute(ffn2_mma, cudaFuncAttributeMaxDynamicSharedMemorySize, SMEM2_BYTES);

    float *g_xc_p, *g_wgc_p, *g_wuc_p, *g_wdc_p;
    cudaGetSymbolAddress((void**)&g_xc_p,  g_xc);
    cudaGetSymbolAddress((void**)&g_wgc_p, g_wgc);
    cudaGetSymbolAddress((void**)&g_wuc_p, g_wuc);
    cudaGetSymbolAddress((void**)&g_wdc_p, g_wdc);

    const int n4x = NT * DD / 4;
    const int n4w = NE * FF * DD / 4;

    // Launch order chosen so ffn1_mma is launch #6 (ncu -s 5 -c 1 profiles it).
    zero_counts_kernel<<<1, 32>>>();                                            // 1
    router_kernel<<<NT / 8, 256>>>(x, Wgate);                                   // 2
    cvt_kernel<<<(n4x + 255) / 256, 256>>>((const float4*)x,  (float4*)g_xc_p,  n4x);   // 3
    cvt_kernel<<<(n4w + 255) / 256, 256>>>((const float4*)Wg, (float4*)g_wgc_p, n4w);   // 4
    cvt_kernel<<<(n4w + 255) / 256, 256>>>((const float4*)Wu, (float4*)g_wuc_p, n4w);   // 5

    dim3 g1(NT / BM, FF / BN, NE);
    ffn1_mma<<<g1, 256, SMEM1_BYTES>>>();                                       // 6

    cvt_kernel<<<(n4w + 255) / 256, 256>>>((const float4*)Wd, (float4*)g_wdc_p, n4w);   // 7

    dim3 g2(NT / BM, DD / BN, NE);
    ffn2_mma<<<g2, 256, SMEM2_BYTES>>>();                                       // 8

    combine_kernel<<<(NT * DD / 4 + 255) / 256, 256>>>((float4*)out);           // 9
}